// round 1
// baseline (speedup 1.0000x reference)
#include <cuda_runtime.h>
#include <cuda_bf16.h>
#include <math.h>

#define S 2048
#define D 4096
#define H 32
#define KVH 8
#define HD 128
#define NREP (H / KVH)   // 4
#define KVD (KVH * HD)   // 1024

// ---------------- scratch (static device arrays; no allocation) ----------------
__device__ float g_q[S * D];        // 32 MB
__device__ float g_k[S * KVD];      // 8 MB
__device__ float g_v[S * KVD];      // 8 MB
__device__ float g_attn[S * D];     // 32 MB

// ---------------- SGEMM: C[M,N] = A[M,K] @ B[K,N], row-major, fp32 ----------------
// 128x128 block tile, BK=8, 256 threads, 8x8 per-thread register tile.
#define BM 128
#define BN 128
#define BK 8
#define TM 8
#define TN 8

__global__ __launch_bounds__(256) void sgemm_kernel(
    const float* __restrict__ A, const float* __restrict__ B,
    float* __restrict__ C, int M, int N, int K)
{
    __shared__ __align__(16) float As[BK][BM];
    __shared__ __align__(16) float Bs[BK][BN];

    const int tid = threadIdx.x;
    const int bx = blockIdx.x * BN;
    const int by = blockIdx.y * BM;

    // A tile loads: 128 rows x 8 cols = 1024 floats = 256 float4
    const int arow = tid >> 1;            // 0..127
    const int acol = (tid & 1) * 4;       // 0 or 4
    // B tile loads: 8 rows x 128 cols = 1024 floats = 256 float4
    const int brow = tid >> 5;            // 0..7
    const int bcol = (tid & 31) * 4;      // 0..124

    const int tx = (tid & 15) * TN;       // col offset in tile
    const int ty = (tid >> 4) * TM;       // row offset in tile

    float acc[TM][TN];
#pragma unroll
    for (int i = 0; i < TM; i++)
#pragma unroll
        for (int j = 0; j < TN; j++) acc[i][j] = 0.0f;

    for (int k0 = 0; k0 < K; k0 += BK) {
        float4 a4 = *reinterpret_cast<const float4*>(&A[(size_t)(by + arow) * K + k0 + acol]);
        As[acol + 0][arow] = a4.x;
        As[acol + 1][arow] = a4.y;
        As[acol + 2][arow] = a4.z;
        As[acol + 3][arow] = a4.w;
        *reinterpret_cast<float4*>(&Bs[brow][bcol]) =
            *reinterpret_cast<const float4*>(&B[(size_t)(k0 + brow) * N + bx + bcol]);
        __syncthreads();

#pragma unroll
        for (int k = 0; k < BK; k++) {
            float4 a0 = *reinterpret_cast<const float4*>(&As[k][ty]);
            float4 a1 = *reinterpret_cast<const float4*>(&As[k][ty + 4]);
            float4 b0 = *reinterpret_cast<const float4*>(&Bs[k][tx]);
            float4 b1 = *reinterpret_cast<const float4*>(&Bs[k][tx + 4]);
            float ra[TM] = {a0.x, a0.y, a0.z, a0.w, a1.x, a1.y, a1.z, a1.w};
            float rb[TN] = {b0.x, b0.y, b0.z, b0.w, b1.x, b1.y, b1.z, b1.w};
#pragma unroll
            for (int i = 0; i < TM; i++)
#pragma unroll
                for (int j = 0; j < TN; j++)
                    acc[i][j] = fmaf(ra[i], rb[j], acc[i][j]);
        }
        __syncthreads();
    }

#pragma unroll
    for (int i = 0; i < TM; i++) {
#pragma unroll
        for (int j = 0; j < TN; j += 4) {
            float4 v = make_float4(acc[i][j], acc[i][j + 1], acc[i][j + 2], acc[i][j + 3]);
            *reinterpret_cast<float4*>(&C[(size_t)(by + ty + i) * N + bx + tx + j]) = v;
        }
    }
}

// ---------------- RoPE (interleaved pairs), in-place ----------------
__global__ void rope_kernel(float* __restrict__ t,
                            const float* __restrict__ cosb,
                            const float* __restrict__ sinb,
                            int nheads)
{
    int idx = blockIdx.x * blockDim.x + threadIdx.x;
    int total = S * nheads * (HD / 2);
    if (idx >= total) return;
    int i = idx & 63;                       // HD/2 = 64
    int head = (idx >> 6) % nheads;
    int pos = idx / (64 * nheads);
    float c = cosb[pos * 64 + i];
    float s = sinb[pos * 64 + i];
    float* p = t + ((size_t)pos * nheads + head) * HD + 2 * i;
    float t0 = p[0], t1 = p[1];
    p[0] = fmaf(t0, c, -t1 * s);
    p[1] = fmaf(t0, s,  t1 * c);
}

// ---------------- causal GQA attention, online softmax ----------------
// One warp handles 4 consecutive query rows of one head (shares K/V loads).
// Block: 128 threads (4 warps) -> 16 query rows per block. Grid: (S/16, H).
__global__ __launch_bounds__(128) void attn_kernel(
    const float* __restrict__ Q, const float* __restrict__ Km,
    const float* __restrict__ Vm, float* __restrict__ O)
{
    const int h = blockIdx.y;
    const int warp = threadIdx.x >> 5;
    const int lane = threadIdx.x & 31;
    const int q0 = blockIdx.x * 16 + warp * 4;
    const int kvh = h / NREP;
    const float scale = 0.08838834764831845f;   // 1/sqrt(128)

    // Q registers: 4 rows x 4 dims (this lane covers dims lane*4 .. lane*4+3)
    float4 q[4];
#pragma unroll
    for (int r = 0; r < 4; r++)
        q[r] = *reinterpret_cast<const float4*>(&Q[(size_t)(q0 + r) * D + h * HD + lane * 4]);

    float m[4], l[4];
    float4 acc[4];
#pragma unroll
    for (int r = 0; r < 4; r++) {
        m[r] = -1e30f; l[r] = 0.0f;
        acc[r] = make_float4(0.f, 0.f, 0.f, 0.f);
    }

    const float* kbase = Km + (size_t)kvh * HD + lane * 4;
    const float* vbase = Vm + (size_t)kvh * HD + lane * 4;

    // main loop: kk in [0, q0] valid for ALL 4 rows (causal)
    for (int kk = 0; kk <= q0; kk++) {
        float4 kv = *reinterpret_cast<const float4*>(kbase + (size_t)kk * KVD);
        float d[4];
#pragma unroll
        for (int r = 0; r < 4; r++) {
            d[r] = q[r].x * kv.x + q[r].y * kv.y + q[r].z * kv.z + q[r].w * kv.w;
        }
#pragma unroll
        for (int off = 16; off > 0; off >>= 1) {
#pragma unroll
            for (int r = 0; r < 4; r++)
                d[r] += __shfl_xor_sync(0xFFFFFFFFu, d[r], off);
        }
        float4 vv = *reinterpret_cast<const float4*>(vbase + (size_t)kk * KVD);
#pragma unroll
        for (int r = 0; r < 4; r++) {
            float sc = d[r] * scale;
            float mn = fmaxf(m[r], sc);
            float corr = __expf(m[r] - mn);
            float p = __expf(sc - mn);
            l[r] = l[r] * corr + p;
            acc[r].x = fmaf(acc[r].x, corr, p * vv.x);
            acc[r].y = fmaf(acc[r].y, corr, p * vv.y);
            acc[r].z = fmaf(acc[r].z, corr, p * vv.z);
            acc[r].w = fmaf(acc[r].w, corr, p * vv.w);
            m[r] = mn;
        }
    }

    // tail: kk = q0+1 .. q0+3, valid only for rows with q0+r >= kk
    for (int kk = q0 + 1; kk <= q0 + 3; kk++) {
        float4 kv = *reinterpret_cast<const float4*>(kbase + (size_t)kk * KVD);
        float d[4];
#pragma unroll
        for (int r = 0; r < 4; r++)
            d[r] = q[r].x * kv.x + q[r].y * kv.y + q[r].z * kv.z + q[r].w * kv.w;
#pragma unroll
        for (int off = 16; off > 0; off >>= 1) {
#pragma unroll
            for (int r = 0; r < 4; r++)
                d[r] += __shfl_xor_sync(0xFFFFFFFFu, d[r], off);
        }
        float4 vv = *reinterpret_cast<const float4*>(vbase + (size_t)kk * KVD);
#pragma unroll
        for (int r = 0; r < 4; r++) {
            if (kk <= q0 + r) {
                float sc = d[r] * scale;
                float mn = fmaxf(m[r], sc);
                float corr = __expf(m[r] - mn);
                float p = __expf(sc - mn);
                l[r] = l[r] * corr + p;
                acc[r].x = fmaf(acc[r].x, corr, p * vv.x);
                acc[r].y = fmaf(acc[r].y, corr, p * vv.y);
                acc[r].z = fmaf(acc[r].z, corr, p * vv.z);
                acc[r].w = fmaf(acc[r].w, corr, p * vv.w);
                m[r] = mn;
            }
        }
    }

#pragma unroll
    for (int r = 0; r < 4; r++) {
        float inv = 1.0f / l[r];
        float4 o = make_float4(acc[r].x * inv, acc[r].y * inv, acc[r].z * inv, acc[r].w * inv);
        *reinterpret_cast<float4*>(&O[(size_t)(q0 + r) * D + h * HD + lane * 4]) = o;
    }
}

// ---------------- launch ----------------
extern "C" void kernel_launch(void* const* d_in, const int* in_sizes, int n_in,
                              void* d_out, int out_size)
{
    const float* x    = (const float*)d_in[0];
    const float* wq   = (const float*)d_in[1];
    const float* wk   = (const float*)d_in[2];
    const float* wv   = (const float*)d_in[3];
    const float* wo   = (const float*)d_in[4];
    const float* cosb = (const float*)d_in[5];
    const float* sinb = (const float*)d_in[6];
    float* out = (float*)d_out;

    float *q, *k, *v, *attn;
    cudaGetSymbolAddress((void**)&q,    g_q);
    cudaGetSymbolAddress((void**)&k,    g_k);
    cudaGetSymbolAddress((void**)&v,    g_v);
    cudaGetSymbolAddress((void**)&attn, g_attn);

    // projections
    sgemm_kernel<<<dim3(D / BN, S / BM), 256>>>(x, wq, q, S, D, D);
    sgemm_kernel<<<dim3(KVD / BN, S / BM), 256>>>(x, wk, k, S, KVD, D);
    sgemm_kernel<<<dim3(KVD / BN, S / BM), 256>>>(x, wv, v, S, KVD, D);

    // RoPE on Q and K
    {
        int totq = S * H * (HD / 2);
        rope_kernel<<<(totq + 255) / 256, 256>>>(q, cosb, sinb, H);
        int totk = S * KVH * (HD / 2);
        rope_kernel<<<(totk + 255) / 256, 256>>>(k, cosb, sinb, KVH);
    }

    // attention
    attn_kernel<<<dim3(S / 16, H), 128>>>(q, k, v, attn);

    // output projection
    sgemm_kernel<<<dim3(D / BN, S / BM), 256>>>(attn, wo, out, S, D, D);
}

// round 3
// speedup vs baseline: 1.5592x; 1.5592x over previous
#include <cuda_runtime.h>
#include <cuda_bf16.h>
#include <cstdint>

#define S 2048
#define D 4096
#define H 32
#define KVH 8
#define HD 128
#define NREP (H / KVH)
#define KVD (KVH * HD)

// ---------------- scratch (static device arrays; no allocation) ----------------
__device__ float g_q[S * D];
__device__ float g_k[S * KVD];
__device__ float g_v[S * KVD];
__device__ float g_attn[S * D];

__device__ __nv_bfloat16 g_xhi[S * D], g_xlo[S * D];
__device__ __nv_bfloat16 g_ahi[S * D], g_alo[S * D];
__device__ __nv_bfloat16 g_wqhi[D * D], g_wqlo[D * D];       // transposed [N,K]
__device__ __nv_bfloat16 g_wkhi[KVD * D], g_wklo[KVD * D];
__device__ __nv_bfloat16 g_wvhi[KVD * D], g_wvlo[KVD * D];
__device__ __nv_bfloat16 g_wohi[D * D], g_wolo[D * D];

// ---------------- helpers ----------------
__device__ __forceinline__ uint32_t s2u(const void* p) {
    uint32_t a;
    asm("{ .reg .u64 t; cvta.to.shared.u64 t, %1; cvt.u32.u64 %0, t; }" : "=r"(a) : "l"(p));
    return a;
}
__device__ __forceinline__ uint32_t lds32(uint32_t addr) {
    uint32_t v;
    asm volatile("ld.shared.b32 %0, [%1];" : "=r"(v) : "r"(addr));
    return v;
}
__device__ __forceinline__ void cpasync16(uint32_t saddr, const void* gaddr) {
    asm volatile("cp.async.cg.shared.global [%0], [%1], 16;" :: "r"(saddr), "l"(gaddr));
}
__device__ __forceinline__ void mma16816(float* d, const uint32_t* a, const uint32_t* b) {
    asm volatile(
        "mma.sync.aligned.m16n8k16.row.col.f32.bf16.bf16.f32 "
        "{%0,%1,%2,%3}, {%4,%5,%6,%7}, {%8,%9}, {%0,%1,%2,%3};"
        : "+f"(d[0]), "+f"(d[1]), "+f"(d[2]), "+f"(d[3])
        : "r"(a[0]), "r"(a[1]), "r"(a[2]), "r"(a[3]), "r"(b[0]), "r"(b[1]));
}

// ---------------- split: fp32 -> (hi, lo) bf16, same layout ----------------
__global__ void split_kernel(const float* __restrict__ in,
                             __nv_bfloat16* __restrict__ hi,
                             __nv_bfloat16* __restrict__ lo, int n4)
{
    int i = blockIdx.x * blockDim.x + threadIdx.x;
    if (i >= n4) return;
    float4 v = reinterpret_cast<const float4*>(in)[i];
    __nv_bfloat16 h0 = __float2bfloat16(v.x), h1 = __float2bfloat16(v.y);
    __nv_bfloat16 h2 = __float2bfloat16(v.z), h3 = __float2bfloat16(v.w);
    __nv_bfloat16 l0 = __float2bfloat16(v.x - __bfloat162float(h0));
    __nv_bfloat16 l1 = __float2bfloat16(v.y - __bfloat162float(h1));
    __nv_bfloat16 l2 = __float2bfloat16(v.z - __bfloat162float(h2));
    __nv_bfloat16 l3 = __float2bfloat16(v.w - __bfloat162float(h3));
    __nv_bfloat162 p;
    p.x = h0; p.y = h1; reinterpret_cast<__nv_bfloat162*>(hi)[2 * i]     = p;
    p.x = h2; p.y = h3; reinterpret_cast<__nv_bfloat162*>(hi)[2 * i + 1] = p;
    p.x = l0; p.y = l1; reinterpret_cast<__nv_bfloat162*>(lo)[2 * i]     = p;
    p.x = l2; p.y = l3; reinterpret_cast<__nv_bfloat162*>(lo)[2 * i + 1] = p;
}

// ---------------- transpose+split: W[K,N] fp32 -> hi/lo bf16 [N,K] ----------------
__global__ void tsplit_kernel(const float* __restrict__ w,
                              __nv_bfloat16* __restrict__ hi,
                              __nv_bfloat16* __restrict__ lo, int K, int N)
{
    __shared__ float t[32][33];
    int n0 = blockIdx.x * 32, k0 = blockIdx.y * 32;
    int tx = threadIdx.x, ty = threadIdx.y;
    for (int r = ty; r < 32; r += 8)
        t[r][tx] = w[(size_t)(k0 + r) * N + n0 + tx];
    __syncthreads();
    for (int r = ty; r < 32; r += 8) {
        float v = t[tx][r];
        __nv_bfloat16 h = __float2bfloat16(v);
        __nv_bfloat16 l = __float2bfloat16(v - __bfloat162float(h));
        size_t o = (size_t)(n0 + r) * K + k0 + tx;
        hi[o] = h; lo[o] = l;
    }
}

// ---------------- mma.sync bf16-split GEMM ----------------
// C[M,N] = A[M,K] * B[N,K]^T. A/B as hi/lo bf16, K-major rows.
// 128x128 tile, BK=32, 256 threads (8 warps of 64x32), double-buffered cp.async.
#define GSTRIDE 80u            // bytes per smem row (conflict-free frag loads)
#define GTILE   (128u * GSTRIDE)   // 10240 B per tile
#define GSTAGE  (4u * GTILE)       // Ahi, Alo, Bhi, Blo

__global__ __launch_bounds__(256) void gemm_kernel(
    const __nv_bfloat16* __restrict__ Ahi, const __nv_bfloat16* __restrict__ Alo,
    const __nv_bfloat16* __restrict__ Bhi, const __nv_bfloat16* __restrict__ Blo,
    float* __restrict__ C, int Ndim, int Kdim)
{
    extern __shared__ char dsm[];
    const uint32_t smem = s2u(dsm);

    const int tid = threadIdx.x;
    const int wid = tid >> 5;
    const int lane = tid & 31;
    const int by = blockIdx.y * 128;
    const int bx = blockIdx.x * 128;

    const int wm = (wid & 1) * 64;     // warp row offset
    const int wn = (wid >> 1) * 32;    // warp col offset

    // per-thread load slots: 2 rows-groups per tile
    const int r0 = tid >> 2;           // 0..63
    const int c0 = tid & 3;            // uint4 within 64B row
    const uint32_t soff0 = (uint32_t)r0 * GSTRIDE + c0 * 16u;
    const uint32_t soff1 = (uint32_t)(r0 + 64) * GSTRIDE + c0 * 16u;

    float acc[4][4][4];
#pragma unroll
    for (int i = 0; i < 4; i++)
#pragma unroll
        for (int j = 0; j < 4; j++)
#pragma unroll
            for (int e = 0; e < 4; e++) acc[i][j][e] = 0.0f;

    const int nchunks = Kdim >> 5;

    auto load_stage = [&](int c, int stage) {
        const uint32_t sb = smem + stage * GSTAGE;
        const int k0 = c << 5;
        const size_t ga0 = (size_t)(by + r0) * Kdim + k0 + c0 * 8;
        const size_t ga1 = (size_t)(by + r0 + 64) * Kdim + k0 + c0 * 8;
        const size_t gb0 = (size_t)(bx + r0) * Kdim + k0 + c0 * 8;
        const size_t gb1 = (size_t)(bx + r0 + 64) * Kdim + k0 + c0 * 8;
        cpasync16(sb + soff0,              Ahi + ga0);
        cpasync16(sb + soff1,              Ahi + ga1);
        cpasync16(sb + GTILE + soff0,      Alo + ga0);
        cpasync16(sb + GTILE + soff1,      Alo + ga1);
        cpasync16(sb + 2 * GTILE + soff0,  Bhi + gb0);
        cpasync16(sb + 2 * GTILE + soff1,  Bhi + gb1);
        cpasync16(sb + 3 * GTILE + soff0,  Blo + gb0);
        cpasync16(sb + 3 * GTILE + soff1,  Blo + gb1);
    };

    load_stage(0, 0);
    asm volatile("cp.async.commit_group;");

    for (int c = 0; c < nchunks; c++) {
        const int stage = c & 1;
        if (c + 1 < nchunks) {
            load_stage(c + 1, stage ^ 1);
            asm volatile("cp.async.commit_group;");
            asm volatile("cp.async.wait_group 1;");
        } else {
            asm volatile("cp.async.wait_group 0;");
        }
        __syncthreads();

        const uint32_t sb  = smem + stage * GSTAGE;
        const uint32_t sAh = sb;
        const uint32_t sAl = sb + GTILE;
        const uint32_t sBh = sb + 2 * GTILE;
        const uint32_t sBl = sb + 3 * GTILE;

#pragma unroll
        for (int k16 = 0; k16 < 32; k16 += 16) {
            const uint32_t kb = (uint32_t)((lane & 3) * 2 + k16) * 2u;  // byte offset in row
            uint32_t ah[4][4], al[4][4];
#pragma unroll
            for (int fm = 0; fm < 4; fm++) {
                uint32_t ro = (uint32_t)(wm + fm * 16 + (lane >> 2)) * GSTRIDE + kb;
                ah[fm][0] = lds32(sAh + ro);
                ah[fm][1] = lds32(sAh + ro + 8 * GSTRIDE);
                ah[fm][2] = lds32(sAh + ro + 16);
                ah[fm][3] = lds32(sAh + ro + 8 * GSTRIDE + 16);
                al[fm][0] = lds32(sAl + ro);
                al[fm][1] = lds32(sAl + ro + 8 * GSTRIDE);
                al[fm][2] = lds32(sAl + ro + 16);
                al[fm][3] = lds32(sAl + ro + 8 * GSTRIDE + 16);
            }
#pragma unroll
            for (int fn = 0; fn < 4; fn++) {
                uint32_t ro = (uint32_t)(wn + fn * 8 + (lane >> 2)) * GSTRIDE + kb;
                uint32_t bh[2], bl[2];
                bh[0] = lds32(sBh + ro);
                bh[1] = lds32(sBh + ro + 16);
                bl[0] = lds32(sBl + ro);
                bl[1] = lds32(sBl + ro + 16);
#pragma unroll
                for (int fm = 0; fm < 4; fm++) {
                    mma16816(acc[fm][fn], ah[fm], bh);
                    mma16816(acc[fm][fn], al[fm], bh);
                    mma16816(acc[fm][fn], ah[fm], bl);
                }
            }
        }
        __syncthreads();
    }

    // epilogue: m16n8 fragment layout -> C
    const int erow = lane >> 2;
    const int ecol = (lane & 3) * 2;
#pragma unroll
    for (int fm = 0; fm < 4; fm++) {
#pragma unroll
        for (int fn = 0; fn < 4; fn++) {
            float* cp0 = C + (size_t)(by + wm + fm * 16 + erow) * Ndim + bx + wn + fn * 8 + ecol;
            float* cp1 = cp0 + 8 * (size_t)Ndim;
            *reinterpret_cast<float2*>(cp0) = make_float2(acc[fm][fn][0], acc[fm][fn][1]);
            *reinterpret_cast<float2*>(cp1) = make_float2(acc[fm][fn][2], acc[fm][fn][3]);
        }
    }
}

// ---------------- RoPE (interleaved pairs), in-place ----------------
__global__ void rope_kernel(float* __restrict__ t,
                            const float* __restrict__ cosb,
                            const float* __restrict__ sinb, int nheads)
{
    int idx = blockIdx.x * blockDim.x + threadIdx.x;
    int total = S * nheads * (HD / 2);
    if (idx >= total) return;
    int i = idx & 63;
    int head = (idx >> 6) % nheads;
    int pos = idx / (64 * nheads);
    float c = cosb[pos * 64 + i];
    float s = sinb[pos * 64 + i];
    float* p = t + ((size_t)pos * nheads + head) * HD + 2 * i;
    float t0 = p[0], t1 = p[1];
    p[0] = fmaf(t0, c, -t1 * s);
    p[1] = fmaf(t0, s, t1 * c);
}

// ---------------- causal GQA attention, online softmax (fp32) ----------------
__global__ __launch_bounds__(128) void attn_kernel(
    const float* __restrict__ Q, const float* __restrict__ Km,
    const float* __restrict__ Vm, float* __restrict__ O)
{
    const int h = blockIdx.y;
    const int warp = threadIdx.x >> 5;
    const int lane = threadIdx.x & 31;
    const int q0 = blockIdx.x * 16 + warp * 4;
    const int kvh = h / NREP;
    const float scale = 0.08838834764831845f;

    float4 q[4];
#pragma unroll
    for (int r = 0; r < 4; r++)
        q[r] = *reinterpret_cast<const float4*>(&Q[(size_t)(q0 + r) * D + h * HD + lane * 4]);

    float m[4], l[4];
    float4 acc[4];
#pragma unroll
    for (int r = 0; r < 4; r++) {
        m[r] = -1e30f; l[r] = 0.0f;
        acc[r] = make_float4(0.f, 0.f, 0.f, 0.f);
    }

    const float* kbase = Km + (size_t)kvh * HD + lane * 4;
    const float* vbase = Vm + (size_t)kvh * HD + lane * 4;

    for (int kk = 0; kk <= q0; kk++) {
        float4 kv = *reinterpret_cast<const float4*>(kbase + (size_t)kk * KVD);
        float d[4];
#pragma unroll
        for (int r = 0; r < 4; r++)
            d[r] = q[r].x * kv.x + q[r].y * kv.y + q[r].z * kv.z + q[r].w * kv.w;
#pragma unroll
        for (int off = 16; off > 0; off >>= 1) {
#pragma unroll
            for (int r = 0; r < 4; r++)
                d[r] += __shfl_xor_sync(0xFFFFFFFFu, d[r], off);
        }
        float4 vv = *reinterpret_cast<const float4*>(vbase + (size_t)kk * KVD);
#pragma unroll
        for (int r = 0; r < 4; r++) {
            float sc = d[r] * scale;
            float mn = fmaxf(m[r], sc);
            float corr = __expf(m[r] - mn);
            float p = __expf(sc - mn);
            l[r] = l[r] * corr + p;
            acc[r].x = fmaf(acc[r].x, corr, p * vv.x);
            acc[r].y = fmaf(acc[r].y, corr, p * vv.y);
            acc[r].z = fmaf(acc[r].z, corr, p * vv.z);
            acc[r].w = fmaf(acc[r].w, corr, p * vv.w);
            m[r] = mn;
        }
    }
    for (int kk = q0 + 1; kk <= q0 + 3; kk++) {
        float4 kv = *reinterpret_cast<const float4*>(kbase + (size_t)kk * KVD);
        float d[4];
#pragma unroll
        for (int r = 0; r < 4; r++)
            d[r] = q[r].x * kv.x + q[r].y * kv.y + q[r].z * kv.z + q[r].w * kv.w;
#pragma unroll
        for (int off = 16; off > 0; off >>= 1) {
#pragma unroll
            for (int r = 0; r < 4; r++)
                d[r] += __shfl_xor_sync(0xFFFFFFFFu, d[r], off);
        }
        float4 vv = *reinterpret_cast<const float4*>(vbase + (size_t)kk * KVD);
#pragma unroll
        for (int r = 0; r < 4; r++) {
            if (kk <= q0 + r) {
                float sc = d[r] * scale;
                float mn = fmaxf(m[r], sc);
                float corr = __expf(m[r] - mn);
                float p = __expf(sc - mn);
                l[r] = l[r] * corr + p;
                acc[r].x = fmaf(acc[r].x, corr, p * vv.x);
                acc[r].y = fmaf(acc[r].y, corr, p * vv.y);
                acc[r].z = fmaf(acc[r].z, corr, p * vv.z);
                acc[r].w = fmaf(acc[r].w, corr, p * vv.w);
                m[r] = mn;
            }
        }
    }
#pragma unroll
    for (int r = 0; r < 4; r++) {
        float inv = 1.0f / l[r];
        float4 o = make_float4(acc[r].x * inv, acc[r].y * inv, acc[r].z * inv, acc[r].w * inv);
        *reinterpret_cast<float4*>(&O[(size_t)(q0 + r) * D + h * HD + lane * 4]) = o;
    }
}

// ---------------- launch ----------------
extern "C" void kernel_launch(void* const* d_in, const int* in_sizes, int n_in,
                              void* d_out, int out_size)
{
    const float* x    = (const float*)d_in[0];
    const float* wq   = (const float*)d_in[1];
    const float* wk   = (const float*)d_in[2];
    const float* wv   = (const float*)d_in[3];
    const float* wo   = (const float*)d_in[4];
    const float* cosb = (const float*)d_in[5];
    const float* sinb = (const float*)d_in[6];
    float* out = (float*)d_out;

    float *q, *k, *v, *attn;
    cudaGetSymbolAddress((void**)&q, g_q);
    cudaGetSymbolAddress((void**)&k, g_k);
    cudaGetSymbolAddress((void**)&v, g_v);
    cudaGetSymbolAddress((void**)&attn, g_attn);

    __nv_bfloat16 *xhi, *xlo, *ahi, *alo, *wqhi, *wqlo, *wkhi, *wklo, *wvhi, *wvlo, *wohi, *wolo;
    cudaGetSymbolAddress((void**)&xhi, g_xhi);  cudaGetSymbolAddress((void**)&xlo, g_xlo);
    cudaGetSymbolAddress((void**)&ahi, g_ahi);  cudaGetSymbolAddress((void**)&alo, g_alo);
    cudaGetSymbolAddress((void**)&wqhi, g_wqhi); cudaGetSymbolAddress((void**)&wqlo, g_wqlo);
    cudaGetSymbolAddress((void**)&wkhi, g_wkhi); cudaGetSymbolAddress((void**)&wklo, g_wklo);
    cudaGetSymbolAddress((void**)&wvhi, g_wvhi); cudaGetSymbolAddress((void**)&wvlo, g_wvlo);
    cudaGetSymbolAddress((void**)&wohi, g_wohi); cudaGetSymbolAddress((void**)&wolo, g_wolo);

    const int shmem = 2 * GSTAGE;   // 81920 B
    cudaFuncSetAttribute(gemm_kernel, cudaFuncAttributeMaxDynamicSharedMemorySize, shmem);

    // input conversions
    split_kernel<<<(S * D / 4 + 255) / 256, 256>>>(x, xhi, xlo, S * D / 4);
    tsplit_kernel<<<dim3(D / 32, D / 32), dim3(32, 8)>>>(wq, wqhi, wqlo, D, D);
    tsplit_kernel<<<dim3(KVD / 32, D / 32), dim3(32, 8)>>>(wk, wkhi, wklo, D, KVD);
    tsplit_kernel<<<dim3(KVD / 32, D / 32), dim3(32, 8)>>>(wv, wvhi, wvlo, D, KVD);
    tsplit_kernel<<<dim3(D / 32, D / 32), dim3(32, 8)>>>(wo, wohi, wolo, D, D);

    // projections (mma.sync bf16-split)
    gemm_kernel<<<dim3(D / 128, S / 128), 256, shmem>>>(xhi, xlo, wqhi, wqlo, q, D, D);
    gemm_kernel<<<dim3(KVD / 128, S / 128), 256, shmem>>>(xhi, xlo, wkhi, wklo, k, KVD, D);
    gemm_kernel<<<dim3(KVD / 128, S / 128), 256, shmem>>>(xhi, xlo, wvhi, wvlo, v, KVD, D);

    // RoPE
    rope_kernel<<<(S * H * (HD / 2) + 255) / 256, 256>>>(q, cosb, sinb, H);
    rope_kernel<<<(S * KVH * (HD / 2) + 255) / 256, 256>>>(k, cosb, sinb, KVH);

    // attention
    attn_kernel<<<dim3(S / 16, H), 128>>>(q, k, v, attn);

    // output projection
    split_kernel<<<(S * D / 4 + 255) / 256, 256>>>(attn, ahi, alo, S * D / 4);
    gemm_kernel<<<dim3(D / 128, S / 128), 256, shmem>>>(ahi, alo, wohi, wolo, out, D, D);
}

// round 4
// speedup vs baseline: 3.5906x; 2.3028x over previous
#include <cuda_runtime.h>
#include <cuda_bf16.h>
#include <cstdint>

#define S 2048
#define D 4096
#define H 32
#define KVH 8
#define HD 128
#define NREP (H / KVH)
#define KVD (KVH * HD)

// ---------------- scratch (static device arrays; no allocation) ----------------
__device__ float g_q[S * D];
__device__ float g_k[S * KVD];
__device__ float g_v[S * KVD];

__device__ __nv_bfloat16 g_xhi[S * D], g_xlo[S * D];
__device__ __nv_bfloat16 g_ahi[S * D], g_alo[S * D];
__device__ __nv_bfloat16 g_qhi[S * D], g_qlo[S * D];
__device__ __nv_bfloat16 g_khi[S * KVD], g_klo[S * KVD];
__device__ __nv_bfloat16 g_vthi[KVD * S], g_vtlo[KVD * S];
__device__ __nv_bfloat16 g_wqhi[D * D], g_wqlo[D * D];       // transposed [N,K]
__device__ __nv_bfloat16 g_wkhi[KVD * D], g_wklo[KVD * D];
__device__ __nv_bfloat16 g_wvhi[KVD * D], g_wvlo[KVD * D];
__device__ __nv_bfloat16 g_wohi[D * D], g_wolo[D * D];

// ---------------- helpers ----------------
__device__ __forceinline__ uint32_t s2u(const void* p) {
    uint32_t a;
    asm("{ .reg .u64 t; cvta.to.shared.u64 t, %1; cvt.u32.u64 %0, t; }" : "=r"(a) : "l"(p));
    return a;
}
__device__ __forceinline__ uint32_t lds32(uint32_t addr) {
    uint32_t v;
    asm volatile("ld.shared.b32 %0, [%1];" : "=r"(v) : "r"(addr));
    return v;
}
__device__ __forceinline__ void cpasync16(uint32_t saddr, const void* gaddr) {
    asm volatile("cp.async.cg.shared.global [%0], [%1], 16;" :: "r"(saddr), "l"(gaddr));
}
__device__ __forceinline__ void mma16816(float* d, const uint32_t* a, const uint32_t* b) {
    asm volatile(
        "mma.sync.aligned.m16n8k16.row.col.f32.bf16.bf16.f32 "
        "{%0,%1,%2,%3}, {%4,%5,%6,%7}, {%8,%9}, {%0,%1,%2,%3};"
        : "+f"(d[0]), "+f"(d[1]), "+f"(d[2]), "+f"(d[3])
        : "r"(a[0]), "r"(a[1]), "r"(a[2]), "r"(a[3]), "r"(b[0]), "r"(b[1]));
}
__device__ __forceinline__ uint32_t pack_bf16(float x, float y) {
    __nv_bfloat162 t = __floats2bfloat162_rn(x, y);
    return *reinterpret_cast<uint32_t*>(&t);
}

// ---------------- split: fp32 -> (hi, lo) bf16, same layout ----------------
__global__ void split_kernel(const float* __restrict__ in,
                             __nv_bfloat16* __restrict__ hi,
                             __nv_bfloat16* __restrict__ lo, int n4)
{
    int i = blockIdx.x * blockDim.x + threadIdx.x;
    if (i >= n4) return;
    float4 v = reinterpret_cast<const float4*>(in)[i];
    __nv_bfloat16 h0 = __float2bfloat16(v.x), h1 = __float2bfloat16(v.y);
    __nv_bfloat16 h2 = __float2bfloat16(v.z), h3 = __float2bfloat16(v.w);
    __nv_bfloat16 l0 = __float2bfloat16(v.x - __bfloat162float(h0));
    __nv_bfloat16 l1 = __float2bfloat16(v.y - __bfloat162float(h1));
    __nv_bfloat16 l2 = __float2bfloat16(v.z - __bfloat162float(h2));
    __nv_bfloat16 l3 = __float2bfloat16(v.w - __bfloat162float(h3));
    __nv_bfloat162 p;
    p.x = h0; p.y = h1; reinterpret_cast<__nv_bfloat162*>(hi)[2 * i]     = p;
    p.x = h2; p.y = h3; reinterpret_cast<__nv_bfloat162*>(hi)[2 * i + 1] = p;
    p.x = l0; p.y = l1; reinterpret_cast<__nv_bfloat162*>(lo)[2 * i]     = p;
    p.x = l2; p.y = l3; reinterpret_cast<__nv_bfloat162*>(lo)[2 * i + 1] = p;
}

// ---------------- transpose+split: W[K,N] fp32 -> hi/lo bf16 [N,K] ----------------
__global__ void tsplit_kernel(const float* __restrict__ w,
                              __nv_bfloat16* __restrict__ hi,
                              __nv_bfloat16* __restrict__ lo, int K, int N)
{
    __shared__ float t[32][33];
    int n0 = blockIdx.x * 32, k0 = blockIdx.y * 32;
    int tx = threadIdx.x, ty = threadIdx.y;
    for (int r = ty; r < 32; r += 8)
        t[r][tx] = w[(size_t)(k0 + r) * N + n0 + tx];
    __syncthreads();
    for (int r = ty; r < 32; r += 8) {
        float v = t[tx][r];
        __nv_bfloat16 h = __float2bfloat16(v);
        __nv_bfloat16 l = __float2bfloat16(v - __bfloat162float(h));
        size_t o = (size_t)(n0 + r) * K + k0 + tx;
        hi[o] = h; lo[o] = l;
    }
}

// ---------------- RoPE + optional scale + split, fp32 -> bf16 hi/lo ----------------
__global__ void rope_split_kernel(const float* __restrict__ t,
                                  const float* __restrict__ cosb,
                                  const float* __restrict__ sinb,
                                  __nv_bfloat16* __restrict__ hi,
                                  __nv_bfloat16* __restrict__ lo,
                                  int nheads, float scale)
{
    int idx = blockIdx.x * blockDim.x + threadIdx.x;
    int total = S * nheads * (HD / 2);
    if (idx >= total) return;
    int i = idx & 63;
    int head = (idx >> 6) % nheads;
    int pos = idx / (64 * nheads);
    float c = cosb[pos * 64 + i];
    float s = sinb[pos * 64 + i];
    size_t off = ((size_t)pos * nheads + head) * HD + 2 * i;
    const float* p = t + off;
    float t0 = p[0], t1 = p[1];
    float o0 = (t0 * c - t1 * s) * scale;
    float o1 = (t0 * s + t1 * c) * scale;
    __nv_bfloat16 h0 = __float2bfloat16(o0), h1 = __float2bfloat16(o1);
    __nv_bfloat16 l0 = __float2bfloat16(o0 - __bfloat162float(h0));
    __nv_bfloat16 l1 = __float2bfloat16(o1 - __bfloat162float(h1));
    __nv_bfloat162 ph; ph.x = h0; ph.y = h1;
    __nv_bfloat162 pl; pl.x = l0; pl.y = l1;
    *reinterpret_cast<__nv_bfloat162*>(hi + off) = ph;
    *reinterpret_cast<__nv_bfloat162*>(lo + off) = pl;
}

// ---------------- mma.sync bf16-split GEMM ----------------
#define GSTRIDE 80u
#define GTILE   (128u * GSTRIDE)
#define GSTAGE  (4u * GTILE)

__global__ __launch_bounds__(256) void gemm_kernel(
    const __nv_bfloat16* __restrict__ Ahi, const __nv_bfloat16* __restrict__ Alo,
    const __nv_bfloat16* __restrict__ Bhi, const __nv_bfloat16* __restrict__ Blo,
    float* __restrict__ C, int Ndim, int Kdim)
{
    extern __shared__ char dsm[];
    const uint32_t smem = s2u(dsm);

    const int tid = threadIdx.x;
    const int wid = tid >> 5;
    const int lane = tid & 31;
    const int by = blockIdx.y * 128;
    const int bx = blockIdx.x * 128;

    const int wm = (wid & 1) * 64;
    const int wn = (wid >> 1) * 32;

    const int r0 = tid >> 2;
    const int c0 = tid & 3;
    const uint32_t soff0 = (uint32_t)r0 * GSTRIDE + c0 * 16u;
    const uint32_t soff1 = (uint32_t)(r0 + 64) * GSTRIDE + c0 * 16u;

    float acc[4][4][4];
#pragma unroll
    for (int i = 0; i < 4; i++)
#pragma unroll
        for (int j = 0; j < 4; j++)
#pragma unroll
            for (int e = 0; e < 4; e++) acc[i][j][e] = 0.0f;

    const int nchunks = Kdim >> 5;

    auto load_stage = [&](int c, int stage) {
        const uint32_t sb = smem + stage * GSTAGE;
        const int k0 = c << 5;
        const size_t ga0 = (size_t)(by + r0) * Kdim + k0 + c0 * 8;
        const size_t ga1 = (size_t)(by + r0 + 64) * Kdim + k0 + c0 * 8;
        const size_t gb0 = (size_t)(bx + r0) * Kdim + k0 + c0 * 8;
        const size_t gb1 = (size_t)(bx + r0 + 64) * Kdim + k0 + c0 * 8;
        cpasync16(sb + soff0,              Ahi + ga0);
        cpasync16(sb + soff1,              Ahi + ga1);
        cpasync16(sb + GTILE + soff0,      Alo + ga0);
        cpasync16(sb + GTILE + soff1,      Alo + ga1);
        cpasync16(sb + 2 * GTILE + soff0,  Bhi + gb0);
        cpasync16(sb + 2 * GTILE + soff1,  Bhi + gb1);
        cpasync16(sb + 3 * GTILE + soff0,  Blo + gb0);
        cpasync16(sb + 3 * GTILE + soff1,  Blo + gb1);
    };

    load_stage(0, 0);
    asm volatile("cp.async.commit_group;");

    for (int c = 0; c < nchunks; c++) {
        const int stage = c & 1;
        if (c + 1 < nchunks) {
            load_stage(c + 1, stage ^ 1);
            asm volatile("cp.async.commit_group;");
            asm volatile("cp.async.wait_group 1;");
        } else {
            asm volatile("cp.async.wait_group 0;");
        }
        __syncthreads();

        const uint32_t sb  = smem + stage * GSTAGE;
        const uint32_t sAh = sb;
        const uint32_t sAl = sb + GTILE;
        const uint32_t sBh = sb + 2 * GTILE;
        const uint32_t sBl = sb + 3 * GTILE;

#pragma unroll
        for (int k16 = 0; k16 < 32; k16 += 16) {
            const uint32_t kb = (uint32_t)((lane & 3) * 2 + k16) * 2u;
            uint32_t ah[4][4], al[4][4];
#pragma unroll
            for (int fm = 0; fm < 4; fm++) {
                uint32_t ro = (uint32_t)(wm + fm * 16 + (lane >> 2)) * GSTRIDE + kb;
                ah[fm][0] = lds32(sAh + ro);
                ah[fm][1] = lds32(sAh + ro + 8 * GSTRIDE);
                ah[fm][2] = lds32(sAh + ro + 16);
                ah[fm][3] = lds32(sAh + ro + 8 * GSTRIDE + 16);
                al[fm][0] = lds32(sAl + ro);
                al[fm][1] = lds32(sAl + ro + 8 * GSTRIDE);
                al[fm][2] = lds32(sAl + ro + 16);
                al[fm][3] = lds32(sAl + ro + 8 * GSTRIDE + 16);
            }
#pragma unroll
            for (int fn = 0; fn < 4; fn++) {
                uint32_t ro = (uint32_t)(wn + fn * 8 + (lane >> 2)) * GSTRIDE + kb;
                uint32_t bh[2], bl[2];
                bh[0] = lds32(sBh + ro);
                bh[1] = lds32(sBh + ro + 16);
                bl[0] = lds32(sBl + ro);
                bl[1] = lds32(sBl + ro + 16);
#pragma unroll
                for (int fm = 0; fm < 4; fm++) {
                    mma16816(acc[fm][fn], ah[fm], bh);
                    mma16816(acc[fm][fn], al[fm], bh);
                    mma16816(acc[fm][fn], ah[fm], bl);
                }
            }
        }
        __syncthreads();
    }

    const int erow = lane >> 2;
    const int ecol = (lane & 3) * 2;
#pragma unroll
    for (int fm = 0; fm < 4; fm++) {
#pragma unroll
        for (int fn = 0; fn < 4; fn++) {
            float* cp0 = C + (size_t)(by + wm + fm * 16 + erow) * Ndim + bx + wn + fn * 8 + ecol;
            float* cp1 = cp0 + 8 * (size_t)Ndim;
            *reinterpret_cast<float2*>(cp0) = make_float2(acc[fm][fn][0], acc[fm][fn][1]);
            *reinterpret_cast<float2*>(cp1) = make_float2(acc[fm][fn][2], acc[fm][fn][3]);
        }
    }
}

// ---------------- flash attention (mma.sync, bf16 split, online softmax) ----------------
// Block: 64 q rows x 1 head, 4 warps x 16 rows. KV tiles of 64.
// Q/K smem: 64 rows x 272B (128 bf16 + pad). V smem: [hd=128 rows] x 144B (64 bf16 + pad).
#define KPAD 272u
#define VPAD 144u
#define SM_QH 0u
#define SM_QL 17408u
#define SM_KH 34816u
#define SM_KL 52224u
#define SM_VH 69632u
#define SM_VL 88064u
#define SM_TOT 106496u

__global__ __launch_bounds__(128) void fattn_kernel(
    const __nv_bfloat16* __restrict__ Qh, const __nv_bfloat16* __restrict__ Ql,
    const __nv_bfloat16* __restrict__ Kh, const __nv_bfloat16* __restrict__ Kl,
    const __nv_bfloat16* __restrict__ Vth, const __nv_bfloat16* __restrict__ Vtl,
    __nv_bfloat16* __restrict__ Ohi, __nv_bfloat16* __restrict__ Olo)
{
    extern __shared__ char dsm[];
    const uint32_t smem = s2u(dsm);
    const int tid = threadIdx.x;
    const int wid = tid >> 5, lane = tid & 31;
    const int qt = gridDim.x - 1 - blockIdx.x;   // big blocks first
    const int h = blockIdx.y;
    const int kvh = h / NREP;
    const int q0 = qt * 64;

    const int r = lane >> 2;
    const int cgrp = lane & 3;

    // ---- async loads ----
    auto loadK = [&](int t) {
#pragma unroll
        for (int i = 0; i < 8; i++) {
            int idx = tid + i * 128;
            int row = idx >> 4, cc = idx & 15;
            size_t g = (size_t)(t * 64 + row) * KVD + kvh * HD + cc * 8;
            cpasync16(smem + SM_KH + row * KPAD + cc * 16, Kh + g);
            cpasync16(smem + SM_KL + row * KPAD + cc * 16, Kl + g);
        }
    };
    auto loadV = [&](int t) {
#pragma unroll
        for (int i = 0; i < 8; i++) {
            int idx = tid + i * 128;
            int row = idx >> 3, cc = idx & 7;
            size_t g = (size_t)(kvh * HD + row) * S + t * 64 + cc * 8;
            cpasync16(smem + SM_VH + row * VPAD + cc * 16, Vth + g);
            cpasync16(smem + SM_VL + row * VPAD + cc * 16, Vtl + g);
        }
    };

    // Q tile load
#pragma unroll
    for (int i = 0; i < 8; i++) {
        int idx = tid + i * 128;
        int row = idx >> 4, cc = idx & 15;
        size_t g = (size_t)(q0 + row) * D + h * HD + cc * 8;
        cpasync16(smem + SM_QH + row * KPAD + cc * 16, Qh + g);
        cpasync16(smem + SM_QL + row * KPAD + cc * 16, Ql + g);
    }
    loadK(0);
    asm volatile("cp.async.commit_group;");

    float m0 = -1e30f, m1 = -1e30f, l0 = 0.0f, l1 = 0.0f;
    float oacc[16][4];
#pragma unroll
    for (int f = 0; f < 16; f++)
#pragma unroll
        for (int e = 0; e < 4; e++) oacc[f][e] = 0.0f;

    const int rowA = wid * 16 + r;     // local q row (elems 0,1)
    const int rowB = rowA + 8;         // local q row (elems 2,3)

    for (int t = 0; t <= qt; t++) {
        asm volatile("cp.async.wait_group 0;");
        __syncthreads();
        loadV(t);
        asm volatile("cp.async.commit_group;");

        // ---- S = Q K^T (3-term split, fp32 accurate) ----
        float sacc[8][4];
#pragma unroll
        for (int f = 0; f < 8; f++)
#pragma unroll
            for (int e = 0; e < 4; e++) sacc[f][e] = 0.0f;

#pragma unroll
        for (int ks = 0; ks < 8; ks++) {
            const uint32_t kb = ks * 32u + cgrp * 4u;
            uint32_t qo = smem + SM_QH + (uint32_t)rowA * KPAD + kb;
            uint32_t ah[4], al[4];
            ah[0] = lds32(qo);
            ah[1] = lds32(qo + 8 * KPAD);
            ah[2] = lds32(qo + 16);
            ah[3] = lds32(qo + 8 * KPAD + 16);
            qo += (SM_QL - SM_QH);
            al[0] = lds32(qo);
            al[1] = lds32(qo + 8 * KPAD);
            al[2] = lds32(qo + 16);
            al[3] = lds32(qo + 8 * KPAD + 16);
#pragma unroll
            for (int fn = 0; fn < 8; fn++) {
                uint32_t ko = smem + SM_KH + (uint32_t)(fn * 8 + r) * KPAD + kb;
                uint32_t bh[2], bl[2];
                bh[0] = lds32(ko);
                bh[1] = lds32(ko + 16);
                bl[0] = lds32(ko + (SM_KL - SM_KH));
                bl[1] = lds32(ko + (SM_KL - SM_KH) + 16);
                mma16816(sacc[fn], ah, bh);
                mma16816(sacc[fn], al, bh);
                mma16816(sacc[fn], ah, bl);
            }
        }

        // ---- causal mask (diagonal tile only) ----
        if (t == qt) {
#pragma unroll
            for (int fn = 0; fn < 8; fn++) {
                int c0 = fn * 8 + cgrp * 2;
                if (c0 > rowA) sacc[fn][0] = -1e30f;
                if (c0 + 1 > rowA) sacc[fn][1] = -1e30f;
                if (c0 > rowB) sacc[fn][2] = -1e30f;
                if (c0 + 1 > rowB) sacc[fn][3] = -1e30f;
            }
        }

        // ---- online softmax ----
        float tm0 = -1e30f, tm1 = -1e30f;
#pragma unroll
        for (int fn = 0; fn < 8; fn++) {
            tm0 = fmaxf(tm0, fmaxf(sacc[fn][0], sacc[fn][1]));
            tm1 = fmaxf(tm1, fmaxf(sacc[fn][2], sacc[fn][3]));
        }
        tm0 = fmaxf(tm0, __shfl_xor_sync(0xFFFFFFFFu, tm0, 1));
        tm0 = fmaxf(tm0, __shfl_xor_sync(0xFFFFFFFFu, tm0, 2));
        tm1 = fmaxf(tm1, __shfl_xor_sync(0xFFFFFFFFu, tm1, 1));
        tm1 = fmaxf(tm1, __shfl_xor_sync(0xFFFFFFFFu, tm1, 2));

        float mn0 = fmaxf(m0, tm0), mn1 = fmaxf(m1, tm1);
        float corr0 = __expf(m0 - mn0), corr1 = __expf(m1 - mn1);
        m0 = mn0; m1 = mn1;

        float rs0 = 0.0f, rs1 = 0.0f;
#pragma unroll
        for (int fn = 0; fn < 8; fn++) {
            sacc[fn][0] = __expf(sacc[fn][0] - m0);
            sacc[fn][1] = __expf(sacc[fn][1] - m0);
            sacc[fn][2] = __expf(sacc[fn][2] - m1);
            sacc[fn][3] = __expf(sacc[fn][3] - m1);
            rs0 += sacc[fn][0] + sacc[fn][1];
            rs1 += sacc[fn][2] + sacc[fn][3];
        }
        rs0 += __shfl_xor_sync(0xFFFFFFFFu, rs0, 1);
        rs0 += __shfl_xor_sync(0xFFFFFFFFu, rs0, 2);
        rs1 += __shfl_xor_sync(0xFFFFFFFFu, rs1, 1);
        rs1 += __shfl_xor_sync(0xFFFFFFFFu, rs1, 2);
        l0 = l0 * corr0 + rs0;
        l1 = l1 * corr1 + rs1;

#pragma unroll
        for (int f = 0; f < 16; f++) {
            oacc[f][0] *= corr0; oacc[f][1] *= corr0;
            oacc[f][2] *= corr1; oacc[f][3] *= corr1;
        }

        // ---- wait V, prefetch next K ----
        asm volatile("cp.async.wait_group 0;");
        __syncthreads();
        if (t < qt) {
            loadK(t + 1);
            asm volatile("cp.async.commit_group;");
        }

        // ---- O += P V (P split hi/lo, V split hi/lo, 3 terms) ----
#pragma unroll
        for (int kk = 0; kk < 4; kk++) {
            uint32_t aph[4], apl[4];
#pragma unroll
            for (int half = 0; half < 2; half++) {
                const float* sp = sacc[2 * kk + half];
                float h0 = __bfloat162float(__float2bfloat16(sp[0]));
                float h1 = __bfloat162float(__float2bfloat16(sp[1]));
                float h2 = __bfloat162float(__float2bfloat16(sp[2]));
                float h3 = __bfloat162float(__float2bfloat16(sp[3]));
                aph[half * 2 + 0] = pack_bf16(sp[0], sp[1]);
                aph[half * 2 + 1] = pack_bf16(sp[2], sp[3]);
                apl[half * 2 + 0] = pack_bf16(sp[0] - h0, sp[1] - h1);
                apl[half * 2 + 1] = pack_bf16(sp[2] - h2, sp[3] - h3);
            }
            // reorder: a0 = (row r, k lo8) [half0 reg0], a1 = (row r+8, k lo8) [half0 reg1],
            //          a2 = (row r, k hi8) [half1 reg0], a3 = (row r+8, k hi8) [half1 reg1]
            uint32_t ah[4] = {aph[0], aph[1], aph[2], aph[3]};
            uint32_t al[4] = {apl[0], apl[1], apl[2], apl[3]};
#pragma unroll
            for (int fn = 0; fn < 16; fn++) {
                uint32_t vo = smem + SM_VH + (uint32_t)(fn * 8 + r) * VPAD + kk * 32u + cgrp * 4u;
                uint32_t bh[2], bl[2];
                bh[0] = lds32(vo);
                bh[1] = lds32(vo + 16);
                bl[0] = lds32(vo + (SM_VL - SM_VH));
                bl[1] = lds32(vo + (SM_VL - SM_VH) + 16);
                mma16816(oacc[fn], ah, bh);
                mma16816(oacc[fn], al, bh);
                mma16816(oacc[fn], ah, bl);
            }
        }
    }

    // ---- epilogue: divide by l, write bf16 hi/lo directly ----
    float inv0 = 1.0f / l0, inv1 = 1.0f / l1;
    const size_t gr0 = (size_t)(q0 + rowA) * D + h * HD + cgrp * 2;
    const size_t gr1 = (size_t)(q0 + rowB) * D + h * HD + cgrp * 2;
#pragma unroll
    for (int fn = 0; fn < 16; fn++) {
        float v0 = oacc[fn][0] * inv0, v1 = oacc[fn][1] * inv0;
        float v2 = oacc[fn][2] * inv1, v3 = oacc[fn][3] * inv1;
        __nv_bfloat16 h0 = __float2bfloat16(v0), h1 = __float2bfloat16(v1);
        __nv_bfloat16 h2 = __float2bfloat16(v2), h3 = __float2bfloat16(v3);
        __nv_bfloat162 p;
        p.x = h0; p.y = h1;
        *reinterpret_cast<__nv_bfloat162*>(Ohi + gr0 + fn * 8) = p;
        p.x = __float2bfloat16(v0 - __bfloat162float(h0));
        p.y = __float2bfloat16(v1 - __bfloat162float(h1));
        *reinterpret_cast<__nv_bfloat162*>(Olo + gr0 + fn * 8) = p;
        p.x = h2; p.y = h3;
        *reinterpret_cast<__nv_bfloat162*>(Ohi + gr1 + fn * 8) = p;
        p.x = __float2bfloat16(v2 - __bfloat162float(h2));
        p.y = __float2bfloat16(v3 - __bfloat162float(h3));
        *reinterpret_cast<__nv_bfloat162*>(Olo + gr1 + fn * 8) = p;
    }
}

// ---------------- launch ----------------
extern "C" void kernel_launch(void* const* d_in, const int* in_sizes, int n_in,
                              void* d_out, int out_size)
{
    const float* x    = (const float*)d_in[0];
    const float* wq   = (const float*)d_in[1];
    const float* wk   = (const float*)d_in[2];
    const float* wv   = (const float*)d_in[3];
    const float* wo   = (const float*)d_in[4];
    const float* cosb = (const float*)d_in[5];
    const float* sinb = (const float*)d_in[6];
    float* out = (float*)d_out;

    float *q, *k, *v;
    cudaGetSymbolAddress((void**)&q, g_q);
    cudaGetSymbolAddress((void**)&k, g_k);
    cudaGetSymbolAddress((void**)&v, g_v);

    __nv_bfloat16 *xhi, *xlo, *ahi, *alo, *qhi, *qlo, *khi, *klo, *vthi, *vtlo;
    __nv_bfloat16 *wqhi, *wqlo, *wkhi, *wklo, *wvhi, *wvlo, *wohi, *wolo;
    cudaGetSymbolAddress((void**)&xhi, g_xhi);   cudaGetSymbolAddress((void**)&xlo, g_xlo);
    cudaGetSymbolAddress((void**)&ahi, g_ahi);   cudaGetSymbolAddress((void**)&alo, g_alo);
    cudaGetSymbolAddress((void**)&qhi, g_qhi);   cudaGetSymbolAddress((void**)&qlo, g_qlo);
    cudaGetSymbolAddress((void**)&khi, g_khi);   cudaGetSymbolAddress((void**)&klo, g_klo);
    cudaGetSymbolAddress((void**)&vthi, g_vthi); cudaGetSymbolAddress((void**)&vtlo, g_vtlo);
    cudaGetSymbolAddress((void**)&wqhi, g_wqhi); cudaGetSymbolAddress((void**)&wqlo, g_wqlo);
    cudaGetSymbolAddress((void**)&wkhi, g_wkhi); cudaGetSymbolAddress((void**)&wklo, g_wklo);
    cudaGetSymbolAddress((void**)&wvhi, g_wvhi); cudaGetSymbolAddress((void**)&wvlo, g_wvlo);
    cudaGetSymbolAddress((void**)&wohi, g_wohi); cudaGetSymbolAddress((void**)&wolo, g_wolo);

    const int shmem = 2 * GSTAGE;
    cudaFuncSetAttribute(gemm_kernel, cudaFuncAttributeMaxDynamicSharedMemorySize, shmem);
    cudaFuncSetAttribute(fattn_kernel, cudaFuncAttributeMaxDynamicSharedMemorySize, (int)SM_TOT);

    // input conversions
    split_kernel<<<(S * D / 4 + 255) / 256, 256>>>(x, xhi, xlo, S * D / 4);
    tsplit_kernel<<<dim3(D / 32, D / 32), dim3(32, 8)>>>(wq, wqhi, wqlo, D, D);
    tsplit_kernel<<<dim3(KVD / 32, D / 32), dim3(32, 8)>>>(wk, wkhi, wklo, D, KVD);
    tsplit_kernel<<<dim3(KVD / 32, D / 32), dim3(32, 8)>>>(wv, wvhi, wvlo, D, KVD);
    tsplit_kernel<<<dim3(D / 32, D / 32), dim3(32, 8)>>>(wo, wohi, wolo, D, D);

    // projections (mma.sync bf16-split)
    gemm_kernel<<<dim3(D / 128, S / 128), 256, shmem>>>(xhi, xlo, wqhi, wqlo, q, D, D);
    gemm_kernel<<<dim3(KVD / 128, S / 128), 256, shmem>>>(xhi, xlo, wkhi, wklo, k, KVD, D);
    gemm_kernel<<<dim3(KVD / 128, S / 128), 256, shmem>>>(xhi, xlo, wvhi, wvlo, v, KVD, D);

    // RoPE + scale (Q only) + split to bf16 hi/lo
    const float scale = 0.08838834764831845f;   // 1/sqrt(128)
    rope_split_kernel<<<(S * H * 64 + 255) / 256, 256>>>(q, cosb, sinb, qhi, qlo, H, scale);
    rope_split_kernel<<<(S * KVH * 64 + 255) / 256, 256>>>(k, cosb, sinb, khi, klo, KVH, 1.0f);

    // V: transpose + split to [KVD][S]
    tsplit_kernel<<<dim3(KVD / 32, S / 32), dim3(32, 8)>>>(v, vthi, vtlo, S, KVD);

    // flash attention -> bf16 hi/lo directly
    fattn_kernel<<<dim3(S / 64, H), 128, SM_TOT>>>(qhi, qlo, khi, klo, vthi, vtlo, ahi, alo);

    // output projection
    gemm_kernel<<<dim3(D / 128, S / 128), 256, shmem>>>(ahi, alo, wohi, wolo, out, D, D);
}

// round 5
// speedup vs baseline: 3.9758x; 1.1073x over previous
#include <cuda_runtime.h>
#include <cuda_bf16.h>
#include <cstdint>

#define S 2048
#define D 4096
#define H 32
#define KVH 8
#define HD 128
#define NREP (H / KVH)
#define KVD (KVH * HD)

// ---------------- scratch (static device arrays; no allocation) ----------------
__device__ float g_q[S * D];
__device__ float g_k[S * KVD];
__device__ float g_v[S * KVD];

__device__ __nv_bfloat16 g_xhi[S * D], g_xlo[S * D];
__device__ __nv_bfloat16 g_ahi[S * D], g_alo[S * D];
__device__ __nv_bfloat16 g_qhi[S * D], g_qlo[S * D];
__device__ __nv_bfloat16 g_khi[S * KVD], g_klo[S * KVD];
__device__ __nv_bfloat16 g_vthi[KVD * S], g_vtlo[KVD * S];
__device__ __nv_bfloat16 g_wqhi[D * D], g_wqlo[D * D];       // transposed [N,K]
__device__ __nv_bfloat16 g_wkhi[KVD * D], g_wklo[KVD * D];
__device__ __nv_bfloat16 g_wvhi[KVD * D], g_wvlo[KVD * D];
__device__ __nv_bfloat16 g_wohi[D * D], g_wolo[D * D];

// ---------------- helpers ----------------
__device__ __forceinline__ uint32_t s2u(const void* p) {
    uint32_t a;
    asm("{ .reg .u64 t; cvta.to.shared.u64 t, %1; cvt.u32.u64 %0, t; }" : "=r"(a) : "l"(p));
    return a;
}
__device__ __forceinline__ void cpasync16(uint32_t saddr, const void* gaddr) {
    asm volatile("cp.async.cg.shared.global [%0], [%1], 16;" :: "r"(saddr), "l"(gaddr));
}
__device__ __forceinline__ void ldmx4(uint32_t* r, uint32_t addr) {
    asm volatile("ldmatrix.sync.aligned.m8n8.x4.shared.b16 {%0,%1,%2,%3}, [%4];"
                 : "=r"(r[0]), "=r"(r[1]), "=r"(r[2]), "=r"(r[3]) : "r"(addr));
}
__device__ __forceinline__ void mma16816(float* d, const uint32_t* a, const uint32_t* b) {
    asm volatile(
        "mma.sync.aligned.m16n8k16.row.col.f32.bf16.bf16.f32 "
        "{%0,%1,%2,%3}, {%4,%5,%6,%7}, {%8,%9}, {%0,%1,%2,%3};"
        : "+f"(d[0]), "+f"(d[1]), "+f"(d[2]), "+f"(d[3])
        : "r"(a[0]), "r"(a[1]), "r"(a[2]), "r"(a[3]), "r"(b[0]), "r"(b[1]));
}
__device__ __forceinline__ uint32_t pack_bf16(float x, float y) {
    __nv_bfloat162 t = __floats2bfloat162_rn(x, y);
    return *reinterpret_cast<uint32_t*>(&t);
}

// ---------------- split: fp32 -> (hi, lo) bf16, same layout ----------------
__global__ void split_kernel(const float* __restrict__ in,
                             __nv_bfloat16* __restrict__ hi,
                             __nv_bfloat16* __restrict__ lo, int n4)
{
    int i = blockIdx.x * blockDim.x + threadIdx.x;
    if (i >= n4) return;
    float4 v = reinterpret_cast<const float4*>(in)[i];
    __nv_bfloat16 h0 = __float2bfloat16(v.x), h1 = __float2bfloat16(v.y);
    __nv_bfloat16 h2 = __float2bfloat16(v.z), h3 = __float2bfloat16(v.w);
    __nv_bfloat16 l0 = __float2bfloat16(v.x - __bfloat162float(h0));
    __nv_bfloat16 l1 = __float2bfloat16(v.y - __bfloat162float(h1));
    __nv_bfloat16 l2 = __float2bfloat16(v.z - __bfloat162float(h2));
    __nv_bfloat16 l3 = __float2bfloat16(v.w - __bfloat162float(h3));
    __nv_bfloat162 p;
    p.x = h0; p.y = h1; reinterpret_cast<__nv_bfloat162*>(hi)[2 * i]     = p;
    p.x = h2; p.y = h3; reinterpret_cast<__nv_bfloat162*>(hi)[2 * i + 1] = p;
    p.x = l0; p.y = l1; reinterpret_cast<__nv_bfloat162*>(lo)[2 * i]     = p;
    p.x = l2; p.y = l3; reinterpret_cast<__nv_bfloat162*>(lo)[2 * i + 1] = p;
}

// ---------------- transpose+split: W[K,N] fp32 -> hi/lo bf16 [N,K] ----------------
__global__ void tsplit_kernel(const float* __restrict__ w,
                              __nv_bfloat16* __restrict__ hi,
                              __nv_bfloat16* __restrict__ lo, int K, int N)
{
    __shared__ float t[32][33];
    int n0 = blockIdx.x * 32, k0 = blockIdx.y * 32;
    int tx = threadIdx.x, ty = threadIdx.y;
    for (int r = ty; r < 32; r += 8)
        t[r][tx] = w[(size_t)(k0 + r) * N + n0 + tx];
    __syncthreads();
    for (int r = ty; r < 32; r += 8) {
        float v = t[tx][r];
        __nv_bfloat16 h = __float2bfloat16(v);
        __nv_bfloat16 l = __float2bfloat16(v - __bfloat162float(h));
        size_t o = (size_t)(n0 + r) * K + k0 + tx;
        hi[o] = h; lo[o] = l;
    }
}

// ---------------- RoPE + optional scale + split, fp32 -> bf16 hi/lo ----------------
__global__ void rope_split_kernel(const float* __restrict__ t,
                                  const float* __restrict__ cosb,
                                  const float* __restrict__ sinb,
                                  __nv_bfloat16* __restrict__ hi,
                                  __nv_bfloat16* __restrict__ lo,
                                  int nheads, float scale)
{
    int idx = blockIdx.x * blockDim.x + threadIdx.x;
    int total = S * nheads * (HD / 2);
    if (idx >= total) return;
    int i = idx & 63;
    int head = (idx >> 6) % nheads;
    int pos = idx / (64 * nheads);
    float c = cosb[pos * 64 + i];
    float s = sinb[pos * 64 + i];
    size_t off = ((size_t)pos * nheads + head) * HD + 2 * i;
    const float* p = t + off;
    float t0 = p[0], t1 = p[1];
    float o0 = (t0 * c - t1 * s) * scale;
    float o1 = (t0 * s + t1 * c) * scale;
    __nv_bfloat16 h0 = __float2bfloat16(o0), h1 = __float2bfloat16(o1);
    __nv_bfloat16 l0 = __float2bfloat16(o0 - __bfloat162float(h0));
    __nv_bfloat16 l1 = __float2bfloat16(o1 - __bfloat162float(h1));
    __nv_bfloat162 ph; ph.x = h0; ph.y = h1;
    __nv_bfloat162 pl; pl.x = l0; pl.y = l1;
    *reinterpret_cast<__nv_bfloat162*>(hi + off) = ph;
    *reinterpret_cast<__nv_bfloat162*>(lo + off) = pl;
}

// ---------------- mma.sync bf16-split GEMM v2 ----------------
// 128x128 tile, BK=32, 128 threads (4 warps of 64x64), 3-stage cp.async,
// XOR-swizzled 64B rows, ldmatrix fragment loads.
#define GTILE  8192u               // 128 rows * 64B
#define GSTAGE 32768u              // Ahi, Alo, Bhi, Blo

__global__ __launch_bounds__(128) void gemm_kernel(
    const __nv_bfloat16* __restrict__ Ahi, const __nv_bfloat16* __restrict__ Alo,
    const __nv_bfloat16* __restrict__ Bhi_, const __nv_bfloat16* __restrict__ Blo_,
    float* __restrict__ C_, int Ndim, int Kdim,
    const __nv_bfloat16* __restrict__ Bhi2, const __nv_bfloat16* __restrict__ Blo2,
    float* __restrict__ C2, int nx1)
{
    extern __shared__ char dsm[];
    const uint32_t smem = s2u(dsm);

    const int tid = threadIdx.x;
    const int wid = tid >> 5;
    const int lane = tid & 31;
    const int by = blockIdx.y * 128;

    const __nv_bfloat16* Bhi = Bhi_;
    const __nv_bfloat16* Blo = Blo_;
    float* C = C_;
    int bxi = blockIdx.x;
    if (bxi >= nx1) { Bhi = Bhi2; Blo = Blo2; C = C2; bxi -= nx1; }
    const int bx = bxi * 128;

    const int wm = (wid & 1) * 64;
    const int wn = (wid >> 1) * 64;

    const int grp = lane >> 3;
    const int ri = lane & 7;

    float acc[4][8][4];
#pragma unroll
    for (int i = 0; i < 4; i++)
#pragma unroll
        for (int j = 0; j < 8; j++)
#pragma unroll
            for (int e = 0; e < 4; e++) acc[i][j][e] = 0.0f;

    const int nchunks = Kdim >> 5;

    auto load_stage = [&](int c, int stage) {
        const uint32_t sb = smem + stage * GSTAGE;
        const int k0 = c << 5;
#pragma unroll
        for (int i = 0; i < 4; i++) {
            int idx = tid + i * 128;
            int row = idx >> 2, cc = idx & 3;
            uint32_t sc = (uint32_t)(cc ^ ((row >> 1) & 3));
            uint32_t so = (uint32_t)row * 64u + sc * 16u;
            size_t ga = (size_t)(by + row) * Kdim + k0 + cc * 8;
            size_t gb = (size_t)(bx + row) * Kdim + k0 + cc * 8;
            cpasync16(sb + so,              Ahi + ga);
            cpasync16(sb + GTILE + so,      Alo + ga);
            cpasync16(sb + 2 * GTILE + so,  Bhi + gb);
            cpasync16(sb + 3 * GTILE + so,  Blo + gb);
        }
    };

    load_stage(0, 0);
    asm volatile("cp.async.commit_group;");
    load_stage(1, 1);
    asm volatile("cp.async.commit_group;");

    for (int c = 0; c < nchunks; c++) {
        if (c + 1 < nchunks) asm volatile("cp.async.wait_group 1;");
        else                 asm volatile("cp.async.wait_group 0;");
        __syncthreads();
        if (c + 2 < nchunks) {
            load_stage(c + 2, (c + 2) % 3);
            asm volatile("cp.async.commit_group;");
        }

        const uint32_t sb = smem + (c % 3) * GSTAGE;

#pragma unroll
        for (int k16 = 0; k16 < 2; k16++) {
            const int lchunk = k16 * 2 + (grp >> 1);
            uint32_t ah[4][4], al[4][4];
#pragma unroll
            for (int fm = 0; fm < 4; fm++) {
                int row = wm + fm * 16 + (grp & 1) * 8 + ri;
                uint32_t ad = sb + (uint32_t)row * 64u
                            + (uint32_t)((lchunk ^ ((row >> 1) & 3)) * 16);
                ldmx4(ah[fm], ad);
                ldmx4(al[fm], ad + GTILE);
            }
#pragma unroll
            for (int fnp = 0; fnp < 4; fnp++) {
                int row = wn + fnp * 16 + (grp & 1) * 8 + ri;
                uint32_t bd = sb + 2 * GTILE + (uint32_t)row * 64u
                            + (uint32_t)((lchunk ^ ((row >> 1) & 3)) * 16);
                uint32_t bh4[4], bl4[4];
                ldmx4(bh4, bd);
                ldmx4(bl4, bd + GTILE);
                uint32_t be[2]  = {bh4[0], bh4[2]};
                uint32_t bo[2]  = {bh4[1], bh4[3]};
                uint32_t ble[2] = {bl4[0], bl4[2]};
                uint32_t blo[2] = {bl4[1], bl4[3]};
#pragma unroll
                for (int fm = 0; fm < 4; fm++) {
                    mma16816(acc[fm][2 * fnp],     ah[fm], be);
                    mma16816(acc[fm][2 * fnp],     al[fm], be);
                    mma16816(acc[fm][2 * fnp],     ah[fm], ble);
                    mma16816(acc[fm][2 * fnp + 1], ah[fm], bo);
                    mma16816(acc[fm][2 * fnp + 1], al[fm], bo);
                    mma16816(acc[fm][2 * fnp + 1], ah[fm], blo);
                }
            }
        }
    }

    const int erow = lane >> 2;
    const int ecol = (lane & 3) * 2;
#pragma unroll
    for (int fm = 0; fm < 4; fm++) {
#pragma unroll
        for (int fn = 0; fn < 8; fn++) {
            float* cp0 = C + (size_t)(by + wm + fm * 16 + erow) * Ndim + bx + wn + fn * 8 + ecol;
            float* cp1 = cp0 + 8 * (size_t)Ndim;
            *reinterpret_cast<float2*>(cp0) = make_float2(acc[fm][fn][0], acc[fm][fn][1]);
            *reinterpret_cast<float2*>(cp1) = make_float2(acc[fm][fn][2], acc[fm][fn][3]);
        }
    }
}

// ---------------- flash attention (mma.sync + ldmatrix, bf16 split) ----------------
#define KPAD 272u
#define VPAD 144u
#define SM_QH 0u
#define SM_QL 17408u
#define SM_KH 34816u
#define SM_KL 52224u
#define SM_VH 69632u
#define SM_VL 88064u
#define SM_TOT 106496u

__global__ __launch_bounds__(128) void fattn_kernel(
    const __nv_bfloat16* __restrict__ Qh, const __nv_bfloat16* __restrict__ Ql,
    const __nv_bfloat16* __restrict__ Kh, const __nv_bfloat16* __restrict__ Kl,
    const __nv_bfloat16* __restrict__ Vth, const __nv_bfloat16* __restrict__ Vtl,
    __nv_bfloat16* __restrict__ Ohi, __nv_bfloat16* __restrict__ Olo)
{
    extern __shared__ char dsm[];
    const uint32_t smem = s2u(dsm);
    const int tid = threadIdx.x;
    const int wid = tid >> 5, lane = tid & 31;
    const int qt = gridDim.x - 1 - blockIdx.x;
    const int h = blockIdx.y;
    const int kvh = h / NREP;
    const int q0 = qt * 64;

    const int r = lane >> 2;
    const int cgrp = lane & 3;
    const int grp = lane >> 3;
    const int ri = lane & 7;

    auto loadK = [&](int t) {
#pragma unroll
        for (int i = 0; i < 8; i++) {
            int idx = tid + i * 128;
            int row = idx >> 4, cc = idx & 15;
            size_t g = (size_t)(t * 64 + row) * KVD + kvh * HD + cc * 8;
            cpasync16(smem + SM_KH + row * KPAD + cc * 16, Kh + g);
            cpasync16(smem + SM_KL + row * KPAD + cc * 16, Kl + g);
        }
    };
    auto loadV = [&](int t) {
#pragma unroll
        for (int i = 0; i < 8; i++) {
            int idx = tid + i * 128;
            int row = idx >> 3, cc = idx & 7;
            size_t g = (size_t)(kvh * HD + row) * S + t * 64 + cc * 8;
            cpasync16(smem + SM_VH + row * VPAD + cc * 16, Vth + g);
            cpasync16(smem + SM_VL + row * VPAD + cc * 16, Vtl + g);
        }
    };

#pragma unroll
    for (int i = 0; i < 8; i++) {
        int idx = tid + i * 128;
        int row = idx >> 4, cc = idx & 15;
        size_t g = (size_t)(q0 + row) * D + h * HD + cc * 8;
        cpasync16(smem + SM_QH + row * KPAD + cc * 16, Qh + g);
        cpasync16(smem + SM_QL + row * KPAD + cc * 16, Ql + g);
    }
    loadK(0);
    asm volatile("cp.async.commit_group;");

    float m0 = -1e30f, m1 = -1e30f, l0 = 0.0f, l1 = 0.0f;
    float oacc[16][4];
#pragma unroll
    for (int f = 0; f < 16; f++)
#pragma unroll
        for (int e = 0; e < 4; e++) oacc[f][e] = 0.0f;

    const int rowA = wid * 16 + r;
    const int rowB = rowA + 8;

    for (int t = 0; t <= qt; t++) {
        asm volatile("cp.async.wait_group 0;");
        __syncthreads();
        loadV(t);
        asm volatile("cp.async.commit_group;");

        // ---- S = Q K^T (ldmatrix + 3-term split) ----
        float sacc[8][4];
#pragma unroll
        for (int f = 0; f < 8; f++)
#pragma unroll
            for (int e = 0; e < 4; e++) sacc[f][e] = 0.0f;

#pragma unroll
        for (int ks = 0; ks < 8; ks++) {
            uint32_t ah[4], al[4];
            {
                int qrow = wid * 16 + (grp & 1) * 8 + ri;
                uint32_t qa = smem + SM_QH + (uint32_t)qrow * KPAD + ks * 32u + (grp >> 1) * 16u;
                ldmx4(ah, qa);
                ldmx4(al, qa + (SM_QL - SM_QH));
            }
#pragma unroll
            for (int fnp = 0; fnp < 4; fnp++) {
                int krow = fnp * 16 + (grp & 1) * 8 + ri;
                uint32_t ka = smem + SM_KH + (uint32_t)krow * KPAD + ks * 32u + (grp >> 1) * 16u;
                uint32_t bh4[4], bl4[4];
                ldmx4(bh4, ka);
                ldmx4(bl4, ka + (SM_KL - SM_KH));
                uint32_t be[2]  = {bh4[0], bh4[2]};
                uint32_t bo[2]  = {bh4[1], bh4[3]};
                uint32_t ble[2] = {bl4[0], bl4[2]};
                uint32_t blo[2] = {bl4[1], bl4[3]};
                mma16816(sacc[2 * fnp],     ah, be);
                mma16816(sacc[2 * fnp],     al, be);
                mma16816(sacc[2 * fnp],     ah, ble);
                mma16816(sacc[2 * fnp + 1], ah, bo);
                mma16816(sacc[2 * fnp + 1], al, bo);
                mma16816(sacc[2 * fnp + 1], ah, blo);
            }
        }

        // ---- causal mask ----
        if (t == qt) {
#pragma unroll
            for (int fn = 0; fn < 8; fn++) {
                int c0 = fn * 8 + cgrp * 2;
                if (c0 > rowA) sacc[fn][0] = -1e30f;
                if (c0 + 1 > rowA) sacc[fn][1] = -1e30f;
                if (c0 > rowB) sacc[fn][2] = -1e30f;
                if (c0 + 1 > rowB) sacc[fn][3] = -1e30f;
            }
        }

        // ---- online softmax ----
        float tm0 = -1e30f, tm1 = -1e30f;
#pragma unroll
        for (int fn = 0; fn < 8; fn++) {
            tm0 = fmaxf(tm0, fmaxf(sacc[fn][0], sacc[fn][1]));
            tm1 = fmaxf(tm1, fmaxf(sacc[fn][2], sacc[fn][3]));
        }
        tm0 = fmaxf(tm0, __shfl_xor_sync(0xFFFFFFFFu, tm0, 1));
        tm0 = fmaxf(tm0, __shfl_xor_sync(0xFFFFFFFFu, tm0, 2));
        tm1 = fmaxf(tm1, __shfl_xor_sync(0xFFFFFFFFu, tm1, 1));
        tm1 = fmaxf(tm1, __shfl_xor_sync(0xFFFFFFFFu, tm1, 2));

        float mn0 = fmaxf(m0, tm0), mn1 = fmaxf(m1, tm1);
        float corr0 = __expf(m0 - mn0), corr1 = __expf(m1 - mn1);
        m0 = mn0; m1 = mn1;

        float rs0 = 0.0f, rs1 = 0.0f;
#pragma unroll
        for (int fn = 0; fn < 8; fn++) {
            sacc[fn][0] = __expf(sacc[fn][0] - m0);
            sacc[fn][1] = __expf(sacc[fn][1] - m0);
            sacc[fn][2] = __expf(sacc[fn][2] - m1);
            sacc[fn][3] = __expf(sacc[fn][3] - m1);
            rs0 += sacc[fn][0] + sacc[fn][1];
            rs1 += sacc[fn][2] + sacc[fn][3];
        }
        rs0 += __shfl_xor_sync(0xFFFFFFFFu, rs0, 1);
        rs0 += __shfl_xor_sync(0xFFFFFFFFu, rs0, 2);
        rs1 += __shfl_xor_sync(0xFFFFFFFFu, rs1, 1);
        rs1 += __shfl_xor_sync(0xFFFFFFFFu, rs1, 2);
        l0 = l0 * corr0 + rs0;
        l1 = l1 * corr1 + rs1;

#pragma unroll
        for (int f = 0; f < 16; f++) {
            oacc[f][0] *= corr0; oacc[f][1] *= corr0;
            oacc[f][2] *= corr1; oacc[f][3] *= corr1;
        }

        asm volatile("cp.async.wait_group 0;");
        __syncthreads();
        if (t < qt) {
            loadK(t + 1);
            asm volatile("cp.async.commit_group;");
        }

        // ---- O += P V ----
#pragma unroll
        for (int kk = 0; kk < 4; kk++) {
            uint32_t aph[4], apl[4];
#pragma unroll
            for (int half = 0; half < 2; half++) {
                const float* sp = sacc[2 * kk + half];
                float h0 = __bfloat162float(__float2bfloat16(sp[0]));
                float h1 = __bfloat162float(__float2bfloat16(sp[1]));
                float h2 = __bfloat162float(__float2bfloat16(sp[2]));
                float h3 = __bfloat162float(__float2bfloat16(sp[3]));
                aph[half * 2 + 0] = pack_bf16(sp[0], sp[1]);
                aph[half * 2 + 1] = pack_bf16(sp[2], sp[3]);
                apl[half * 2 + 0] = pack_bf16(sp[0] - h0, sp[1] - h1);
                apl[half * 2 + 1] = pack_bf16(sp[2] - h2, sp[3] - h3);
            }
#pragma unroll
            for (int fnp = 0; fnp < 8; fnp++) {
                int vrow = fnp * 16 + (grp & 1) * 8 + ri;
                uint32_t va = smem + SM_VH + (uint32_t)vrow * VPAD + kk * 32u + (grp >> 1) * 16u;
                uint32_t bh4[4], bl4[4];
                ldmx4(bh4, va);
                ldmx4(bl4, va + (SM_VL - SM_VH));
                uint32_t be[2]  = {bh4[0], bh4[2]};
                uint32_t bo[2]  = {bh4[1], bh4[3]};
                uint32_t ble[2] = {bl4[0], bl4[2]};
                uint32_t blo[2] = {bl4[1], bl4[3]};
                mma16816(oacc[2 * fnp],     aph, be);
                mma16816(oacc[2 * fnp],     apl, be);
                mma16816(oacc[2 * fnp],     aph, ble);
                mma16816(oacc[2 * fnp + 1], aph, bo);
                mma16816(oacc[2 * fnp + 1], apl, bo);
                mma16816(oacc[2 * fnp + 1], aph, blo);
            }
        }
    }

    // ---- epilogue ----
    float inv0 = 1.0f / l0, inv1 = 1.0f / l1;
    const size_t gr0 = (size_t)(q0 + rowA) * D + h * HD + cgrp * 2;
    const size_t gr1 = (size_t)(q0 + rowB) * D + h * HD + cgrp * 2;
#pragma unroll
    for (int fn = 0; fn < 16; fn++) {
        float v0 = oacc[fn][0] * inv0, v1 = oacc[fn][1] * inv0;
        float v2 = oacc[fn][2] * inv1, v3 = oacc[fn][3] * inv1;
        __nv_bfloat16 h0 = __float2bfloat16(v0), h1 = __float2bfloat16(v1);
        __nv_bfloat16 h2 = __float2bfloat16(v2), h3 = __float2bfloat16(v3);
        __nv_bfloat162 p;
        p.x = h0; p.y = h1;
        *reinterpret_cast<__nv_bfloat162*>(Ohi + gr0 + fn * 8) = p;
        p.x = __float2bfloat16(v0 - __bfloat162float(h0));
        p.y = __float2bfloat16(v1 - __bfloat162float(h1));
        *reinterpret_cast<__nv_bfloat162*>(Olo + gr0 + fn * 8) = p;
        p.x = h2; p.y = h3;
        *reinterpret_cast<__nv_bfloat162*>(Ohi + gr1 + fn * 8) = p;
        p.x = __float2bfloat16(v2 - __bfloat162float(h2));
        p.y = __float2bfloat16(v3 - __bfloat162float(h3));
        *reinterpret_cast<__nv_bfloat162*>(Olo + gr1 + fn * 8) = p;
    }
}

// ---------------- launch ----------------
extern "C" void kernel_launch(void* const* d_in, const int* in_sizes, int n_in,
                              void* d_out, int out_size)
{
    const float* x    = (const float*)d_in[0];
    const float* wq   = (const float*)d_in[1];
    const float* wk   = (const float*)d_in[2];
    const float* wv   = (const float*)d_in[3];
    const float* wo   = (const float*)d_in[4];
    const float* cosb = (const float*)d_in[5];
    const float* sinb = (const float*)d_in[6];
    float* out = (float*)d_out;

    float *q, *k, *v;
    cudaGetSymbolAddress((void**)&q, g_q);
    cudaGetSymbolAddress((void**)&k, g_k);
    cudaGetSymbolAddress((void**)&v, g_v);

    __nv_bfloat16 *xhi, *xlo, *ahi, *alo, *qhi, *qlo, *khi, *klo, *vthi, *vtlo;
    __nv_bfloat16 *wqhi, *wqlo, *wkhi, *wklo, *wvhi, *wvlo, *wohi, *wolo;
    cudaGetSymbolAddress((void**)&xhi, g_xhi);   cudaGetSymbolAddress((void**)&xlo, g_xlo);
    cudaGetSymbolAddress((void**)&ahi, g_ahi);   cudaGetSymbolAddress((void**)&alo, g_alo);
    cudaGetSymbolAddress((void**)&qhi, g_qhi);   cudaGetSymbolAddress((void**)&qlo, g_qlo);
    cudaGetSymbolAddress((void**)&khi, g_khi);   cudaGetSymbolAddress((void**)&klo, g_klo);
    cudaGetSymbolAddress((void**)&vthi, g_vthi); cudaGetSymbolAddress((void**)&vtlo, g_vtlo);
    cudaGetSymbolAddress((void**)&wqhi, g_wqhi); cudaGetSymbolAddress((void**)&wqlo, g_wqlo);
    cudaGetSymbolAddress((void**)&wkhi, g_wkhi); cudaGetSymbolAddress((void**)&wklo, g_wklo);
    cudaGetSymbolAddress((void**)&wvhi, g_wvhi); cudaGetSymbolAddress((void**)&wvlo, g_wvlo);
    cudaGetSymbolAddress((void**)&wohi, g_wohi); cudaGetSymbolAddress((void**)&wolo, g_wolo);

    const int shmem = 3 * (int)GSTAGE;   // 98304
    cudaFuncSetAttribute(gemm_kernel, cudaFuncAttributeMaxDynamicSharedMemorySize, shmem);
    cudaFuncSetAttribute(fattn_kernel, cudaFuncAttributeMaxDynamicSharedMemorySize, (int)SM_TOT);

    // input conversions
    split_kernel<<<(S * D / 4 + 255) / 256, 256>>>(x, xhi, xlo, S * D / 4);
    tsplit_kernel<<<dim3(D / 32, D / 32), dim3(32, 8)>>>(wq, wqhi, wqlo, D, D);
    tsplit_kernel<<<dim3(KVD / 32, D / 32), dim3(32, 8)>>>(wk, wkhi, wklo, D, KVD);
    tsplit_kernel<<<dim3(KVD / 32, D / 32), dim3(32, 8)>>>(wv, wvhi, wvlo, D, KVD);
    tsplit_kernel<<<dim3(D / 32, D / 32), dim3(32, 8)>>>(wo, wohi, wolo, D, D);

    // Q projection
    gemm_kernel<<<dim3(D / 128, S / 128), 128, shmem>>>(
        xhi, xlo, wqhi, wqlo, q, D, D, nullptr, nullptr, nullptr, D / 128);
    // K + V projections merged into one launch
    gemm_kernel<<<dim3(2 * KVD / 128, S / 128), 128, shmem>>>(
        xhi, xlo, wkhi, wklo, k, KVD, D, wvhi, wvlo, v, KVD / 128);

    // RoPE + scale (Q only) + split to bf16 hi/lo
    const float scale = 0.08838834764831845f;
    rope_split_kernel<<<(S * H * 64 + 255) / 256, 256>>>(q, cosb, sinb, qhi, qlo, H, scale);
    rope_split_kernel<<<(S * KVH * 64 + 255) / 256, 256>>>(k, cosb, sinb, khi, klo, KVH, 1.0f);

    // V: transpose + split to [KVD][S]
    tsplit_kernel<<<dim3(KVD / 32, S / 32), dim3(32, 8)>>>(v, vthi, vtlo, S, KVD);

    // flash attention
    fattn_kernel<<<dim3(S / 64, H), 128, SM_TOT>>>(qhi, qlo, khi, klo, vthi, vtlo, ahi, alo);

    // output projection
    gemm_kernel<<<dim3(D / 128, S / 128), 128, shmem>>>(
        ahi, alo, wohi, wolo, out, D, D, nullptr, nullptr, nullptr, D / 128);
}